// round 12
// baseline (speedup 1.0000x reference)
#include <cuda_runtime.h>

// db4 single-level 2D DWT, circular padding (end), stride-2 cross-correlation.
// x: (96, 512, 512) f32 -> out: (96*4, 256, 256) f32, subband order ll,lh,hl,hh.
//
// Column pass FIRST over full-width 16-row stripes with packed f32x2 FMA over
// adjacent column pairs (loaded u64 IS the operand). Col-pass output stored
// de-interleaved (even/odd planes) so the row pass can also use f32x2 FMA over
// adjacent output-column pairs with mostly-free operand pairing.

#define HH   512
#define WW   512
#define OWW  256
#define TH   16            // output rows per block (stripe height)
#define IN_R (2*TH + 6)    // 38 input rows per stripe
#define PP   264           // plane pitch in floats (260 used)
#define NT   256           // threads per block (thread owns 2 input columns)
#define SMEM_BYTES (4 * TH * PP * 4)   // 4 planes (loE, loO, hiE, hiO)

typedef unsigned long long u64;

static __device__ __forceinline__ u64 pk(float a, float b) {
    u64 r; asm("mov.b64 %0, {%1, %2};" : "=l"(r) : "f"(a), "f"(b)); return r;
}
static __device__ __forceinline__ void upk(u64 p, float& a, float& b) {
    asm("mov.b64 {%0, %1}, %2;" : "=f"(a), "=f"(b) : "l"(p));
}
static __device__ __forceinline__ void fma2(u64& d, u64 a, u64 b) {
    asm("fma.rn.f32x2 %0, %1, %2, %0;" : "+l"(d) : "l"(a), "l"(b));
}
static __device__ __forceinline__ void mul2(u64& d, u64 a, u64 b) {
    asm("mul.rn.f32x2 %0, %1, %2;" : "=l"(d) : "l"(a), "l"(b));
}

__global__ __launch_bounds__(NT, 3) void dwt2d_db4_kernel(
    const float* __restrict__ x,
    float* __restrict__ out)
{
    extern __shared__ float sm[];
    float* __restrict__ sEl = sm;                 // col-lo, even cols  [TH][PP]
    float* __restrict__ sOl = sm + TH * PP;       // col-lo, odd cols
    float* __restrict__ sEh = sm + 2 * TH * PP;   // col-hi, even cols
    float* __restrict__ sOh = sm + 3 * TH * PP;   // col-hi, odd cols

    const float FL[8] = {-0.010597401784997278f,  0.032883011666982945f,
                          0.030841381835986965f, -0.18703481171888114f,
                         -0.02798376941698385f,   0.6308807679295904f,
                          0.7148465705525415f,    0.23037781330885523f};
    const float FH[8] = {-0.23037781330885523f,   0.7148465705525415f,
                         -0.6308807679295904f,   -0.02798376941698385f,
                          0.18703481171888114f,   0.030841381835986965f,
                         -0.032883011666982945f, -0.010597401784997278f};

    // dup coefficient pairs, shared by both phases
    u64 CLd[8], CHd[8];
    #pragma unroll
    for (int t = 0; t < 8; t++) {
        CLd[t] = pk(FL[t], FL[t]);
        CHd[t] = pk(FH[t], FH[t]);
    }

    const int tid = threadIdx.x;          // 0..255
    const int sy  = blockIdx.x;           // 0..15 stripe
    const int img = blockIdx.y;           // 0..95
    const int h0  = sy * TH;              // output row base
    const int r0  = 2 * h0;               // input row base

    const float* __restrict__ xin = x + (size_t)img * HH * WW;

    // ---- phase A: column pass, thread owns input columns (2c, 2c+1) ----
    // One aligned u64 load per row IS the FFMA2 operand. Ring of 4 packed
    // accumulator pairs; output j retires at tap t==7 into E/O planes.
    {
        const int c = tid;
        u64 aLo[4], aHi[4];
        #pragma unroll
        for (int k = 0; k < IN_R; k++) {
            int gr = (r0 + k) & (HH - 1);
            u64 v = *(const u64*)(xin + (size_t)gr * WW + 2 * c);
            #pragma unroll
            for (int j = 0; j < TH; j++) {
                const int t = k - 2 * j;
                if (t == 0) {
                    mul2(aLo[j & 3], CLd[0], v);
                    mul2(aHi[j & 3], CHd[0], v);
                } else if (t > 0 && t < 8) {
                    fma2(aLo[j & 3], CLd[t], v);
                    fma2(aHi[j & 3], CHd[t], v);
                }
                if (t == 7) {
                    float l0, l1, g0, g1;
                    upk(aLo[j & 3], l0, l1);      // l0 = col 2c (even), l1 = col 2c+1 (odd)
                    upk(aHi[j & 3], g0, g1);
                    sEl[j * PP + c] = l0;  sOl[j * PP + c] = l1;
                    sEh[j * PP + c] = g0;  sOh[j * PP + c] = g1;
                    if (c < 3) {                  // wrap halo: E/O index 256..258
                        sEl[j * PP + 256 + c] = l0;  sOl[j * PP + 256 + c] = l1;
                        sEh[j * PP + 256 + c] = g0;  sOh[j * PP + 256 + c] = g1;
                    }
                }
            }
        }
    }
    __syncthreads();

    // ---- phase B: row pass from de-interleaved planes, packed over col pairs ----
    // item (pl, j, wp): output cols 2wp, 2wp+1 of output row h0+j, 2 subbands.
    // out_w = sum_m F[2m]*E[w+m] + F[2m+1]*O[w+m]; packed acc = (out_2wp, out_2wp+1),
    // operand m = (E[2wp+m], E[2wp+1+m]) assembled from 3 aligned float2 loads.
    float* __restrict__ outi = out + (size_t)img * 4 * OWW * OWW;
    const size_t SB = (size_t)OWW * OWW;

    #pragma unroll 4
    for (int it = 0; it < 16; it++) {
        int idx = tid + it * NT;             // 0..4095
        int wp  = idx & 127;                 // col-pair index
        int j   = (idx >> 7) & (TH - 1);     // 0..15
        int pl  = idx >> 11;                 // 0..1
        const float* __restrict__ E = (pl ? sEh : sEl) + j * PP + 2 * wp;
        const float* __restrict__ O = (pl ? sOh : sOl) + j * PP + 2 * wp;

        float2 e01 = *(const float2*)(E);
        float2 e23 = *(const float2*)(E + 2);
        float2 e45 = *(const float2*)(E + 4);   // only .x used
        float2 o01 = *(const float2*)(O);
        float2 o23 = *(const float2*)(O + 2);
        float2 o45 = *(const float2*)(O + 4);   // only .x used

        u64 vE0 = pk(e01.x, e01.y);
        u64 vE1 = pk(e01.y, e23.x);
        u64 vE2 = pk(e23.x, e23.y);
        u64 vE3 = pk(e23.y, e45.x);
        u64 vO0 = pk(o01.x, o01.y);
        u64 vO1 = pk(o01.y, o23.x);
        u64 vO2 = pk(o23.x, o23.y);
        u64 vO3 = pk(o23.y, o45.x);

        u64 aL, aH;
        mul2(aL, CLd[0], vE0);  mul2(aH, CHd[0], vE0);
        fma2(aL, CLd[1], vO0);  fma2(aH, CHd[1], vO0);
        fma2(aL, CLd[2], vE1);  fma2(aH, CHd[2], vE1);
        fma2(aL, CLd[3], vO1);  fma2(aH, CHd[3], vO1);
        fma2(aL, CLd[4], vE2);  fma2(aH, CHd[4], vE2);
        fma2(aL, CLd[5], vO2);  fma2(aH, CHd[5], vO2);
        fma2(aL, CLd[6], vE3);  fma2(aH, CHd[6], vE3);
        fma2(aL, CLd[7], vO3);  fma2(aH, CHd[7], vO3);

        int sbL = pl ? 1 : 0;    // row-lo result subband (ll / lh)
        int sbH = pl ? 3 : 2;    // row-hi result subband (hl / hh)
        size_t o = (size_t)(h0 + j) * OWW + 2 * wp;
        *(u64*)(outi + sbL * SB + o) = aL;
        *(u64*)(outi + sbH * SB + o) = aH;
    }
}

extern "C" void kernel_launch(void* const* d_in, const int* in_sizes, int n_in,
                              void* d_out, int out_size)
{
    const float* x = (const float*)d_in[0];   // (32,3,512,512) f32
    float* out = (float*)d_out;               // (32,12,256,256) f32

    cudaFuncSetAttribute(dwt2d_db4_kernel,
                         cudaFuncAttributeMaxDynamicSharedMemorySize, SMEM_BYTES);
    dim3 grid(OWW / TH, 96);                  // (16 stripes, 96 images)
    dwt2d_db4_kernel<<<grid, NT, SMEM_BYTES>>>(x, out);
}

// round 13
// speedup vs baseline: 1.0934x; 1.0934x over previous
#include <cuda_runtime.h>

// db4 single-level 2D DWT, circular padding (end), stride-2 cross-correlation.
// x: (96, 512, 512) f32 -> out: (96*4, 256, 256) f32, subband order ll,lh,hl,hh.
//
// Column pass FIRST (full-width stripes) with packed f32x2 FMA over adjacent
// column pairs (loaded u64 IS the operand). QMF symmetry FH[t]=(-1)^(t+1)FL[7-t]
// lets the hi chain reuse the lo coefficient bank with a per-row sign flip
// (parity of k), halving coefficient registers -> 6 blocks/SM.

#define HH   512
#define WW   512
#define OWW  256
#define TH   8             // output rows per block (stripe height)
#define IN_R (2*TH + 6)    // 22 input rows per stripe
#define PW   520           // plane width: 512 + 8 wrap-halo cols
#define NT   256           // threads per block (thread owns 2 columns)

typedef unsigned long long u64;

static __device__ __forceinline__ u64 pk(float a, float b) {
    u64 r; asm("mov.b64 %0, {%1, %2};" : "=l"(r) : "f"(a), "f"(b)); return r;
}
static __device__ __forceinline__ void fma2(u64& d, u64 a, u64 b) {
    asm("fma.rn.f32x2 %0, %1, %2, %0;" : "+l"(d) : "l"(a), "l"(b));
}
static __device__ __forceinline__ void mul2(u64& d, u64 a, u64 b) {
    asm("mul.rn.f32x2 %0, %1, %2;" : "=l"(d) : "l"(a), "l"(b));
}

__global__ __launch_bounds__(NT, 6) void dwt2d_db4_kernel(
    const float* __restrict__ x,
    float* __restrict__ out)
{
    __shared__ __align__(16) float s_lo[TH][PW];   // col-pass LO plane
    __shared__ __align__(16) float s_hi[TH][PW];   // col-pass HI plane

    const float FL[8] = {-0.010597401784997278f,  0.032883011666982945f,
                          0.030841381835986965f, -0.18703481171888114f,
                         -0.02798376941698385f,   0.6308807679295904f,
                          0.7148465705525415f,    0.23037781330885523f};
    const float FH[8] = {-0.23037781330885523f,   0.7148465705525415f,
                         -0.6308807679295904f,   -0.02798376941698385f,
                          0.18703481171888114f,   0.030841381835986965f,
                         -0.032883011666982945f, -0.010597401784997278f};

    const int tid = threadIdx.x;          // 0..255
    const int sy  = blockIdx.x;           // 0..31 stripe
    const int img = blockIdx.y;           // 0..95
    const int h0  = sy * TH;              // output row base
    const int r0  = 2 * h0;               // input row base

    const float* __restrict__ xin = x + (size_t)img * HH * WW;

    // ---- phase A: column pass, thread owns input columns (2c, 2c+1) ----
    // One aligned u64 load per row IS the FFMA2 operand. Hi chain uses the
    // QMF identity FH[t] = (-1)^(t+1) FL[7-t]: sign folded into the operand
    // (negate v on even k), coefficient bank CLd shared by both chains.
    {
        u64 CLd[8];                         // dup lo-coef pairs only
        #pragma unroll
        for (int t = 0; t < 8; t++) CLd[t] = pk(FL[t], FL[t]);

        const int c = tid;
        u64 aLo[4], aHi[4];                // ring over j&3
        #pragma unroll
        for (int k = 0; k < IN_R; k++) {
            int gr = (r0 + k) & (HH - 1);
            u64 v  = *(const u64*)(xin + (size_t)gr * WW + 2 * c);
            // sign for hi chain: (-1)^(t+1), parity(t) == parity(k)
            u64 vh = (k & 1) ? v : (v ^ 0x8000000080000000ULL);
            #pragma unroll
            for (int j = 0; j < TH; j++) {
                const int t = k - 2 * j;
                if (t == 0) {
                    mul2(aLo[j & 3], CLd[0], v);
                    mul2(aHi[j & 3], CLd[7], vh);
                } else if (t > 0 && t < 8) {
                    fma2(aLo[j & 3], CLd[t],     v);
                    fma2(aHi[j & 3], CLd[7 - t], vh);
                }
                if (t == 7) {
                    *(u64*)&s_lo[j][2 * c] = aLo[j & 3];
                    *(u64*)&s_hi[j][2 * c] = aHi[j & 3];
                    if (c < 4) {                    // wrap halo cols 512..519
                        *(u64*)&s_lo[j][WW + 2 * c] = aLo[j & 3];
                        *(u64*)&s_hi[j][WW + 2 * c] = aHi[j & 3];
                    }
                }
            }
        }
    }
    __syncthreads();

    // ---- phase B: row pass from smem planes (scalar, immediates) ----
    // item = (plane, j, wp): output cols 2wp, 2wp+1 of output row h0+j.
    float* __restrict__ outi = out + (size_t)img * 4 * OWW * OWW;
    const size_t SB = (size_t)OWW * OWW;

    #pragma unroll
    for (int it = 0; it < 8; it++) {
        int idx = tid + it * NT;             // 0..2047
        int wp  = idx & 127;                 // col-pair index
        int j   = (idx >> 7) & (TH - 1);     // 0..7
        int pl  = idx >> 10;                 // 0..1
        const float* __restrict__ A = pl ? &s_hi[j][0] : &s_lo[j][0];

        // window A[4wp .. 4wp+9]; 16B-stride contiguous -> conflict-free
        float4 q0 = *(const float4*)(A + 4 * wp);
        float4 q1 = *(const float4*)(A + 4 * wp + 4);
        float2 q2 = *(const float2*)(A + 4 * wp + 8);
        float v[10] = {q0.x, q0.y, q0.z, q0.w,
                       q1.x, q1.y, q1.z, q1.w,
                       q2.x, q2.y};

        float lo0 = 0.f, hi0 = 0.f, lo1 = 0.f, hi1 = 0.f;
        #pragma unroll
        for (int t = 0; t < 8; t++) {
            lo0 = fmaf(FL[t], v[t],     lo0);
            hi0 = fmaf(FH[t], v[t],     hi0);
            lo1 = fmaf(FL[t], v[t + 2], lo1);
            hi1 = fmaf(FH[t], v[t + 2], hi1);
        }

        int sbL = pl ? 1 : 0;    // row-lo result subband
        int sbH = pl ? 3 : 2;    // row-hi result subband
        size_t o = (size_t)(h0 + j) * OWW + 2 * wp;
        *(float2*)(outi + sbL * SB + o) = make_float2(lo0, lo1);
        *(float2*)(outi + sbH * SB + o) = make_float2(hi0, hi1);
    }
}

extern "C" void kernel_launch(void* const* d_in, const int* in_sizes, int n_in,
                              void* d_out, int out_size)
{
    const float* x = (const float*)d_in[0];   // (32,3,512,512) f32
    float* out = (float*)d_out;               // (32,12,256,256) f32

    dim3 grid(OWW / TH, 96);                  // (32 stripes, 96 images)
    dwt2d_db4_kernel<<<grid, NT>>>(x, out);
}

// round 15
// speedup vs baseline: 1.2132x; 1.1096x over previous
#include <cuda_runtime.h>

// db4 single-level 2D DWT, circular padding (end), stride-2 cross-correlation.
// x: (96, 512, 512) f32 -> out: (96*4, 256, 256) f32, subband order ll,lh,hl,hh.
//
// Column pass FIRST (full-width stripes) with packed f32x2 FMA over adjacent
// column pairs (loaded u64 IS the operand). QMF symmetry shares one coef bank
// between lo/hi chains; the freed registers fund an explicit 4-deep global
// load ring (guaranteed MLP>=4) in phase A.

#define HH   512
#define WW   512
#define OWW  256
#define TH   8             // output rows per block (stripe height)
#define IN_R (2*TH + 6)    // 22 input rows per stripe
#define PW   520           // plane width: 512 + 8 wrap-halo cols
#define NT   256           // threads per block (thread owns 2 columns)

typedef unsigned long long u64;

static __device__ __forceinline__ u64 pk(float a, float b) {
    u64 r; asm("mov.b64 %0, {%1, %2};" : "=l"(r) : "f"(a), "f"(b)); return r;
}
static __device__ __forceinline__ void fma2(u64& d, u64 a, u64 b) {
    asm("fma.rn.f32x2 %0, %1, %2, %0;" : "+l"(d) : "l"(a), "l"(b));
}
static __device__ __forceinline__ void mul2(u64& d, u64 a, u64 b) {
    asm("mul.rn.f32x2 %0, %1, %2;" : "=l"(d) : "l"(a), "l"(b));
}

__global__ __launch_bounds__(NT, 5) void dwt2d_db4_kernel(
    const float* __restrict__ x,
    float* __restrict__ out)
{
    __shared__ __align__(16) float s_lo[TH][PW];   // col-pass LO plane
    __shared__ __align__(16) float s_hi[TH][PW];   // col-pass HI plane

    const float FL[8] = {-0.010597401784997278f,  0.032883011666982945f,
                          0.030841381835986965f, -0.18703481171888114f,
                         -0.02798376941698385f,   0.6308807679295904f,
                          0.7148465705525415f,    0.23037781330885523f};
    const float FH[8] = {-0.23037781330885523f,   0.7148465705525415f,
                         -0.6308807679295904f,   -0.02798376941698385f,
                          0.18703481171888114f,   0.030841381835986965f,
                         -0.032883011666982945f, -0.010597401784997278f};

    const int tid = threadIdx.x;          // 0..255
    const int sy  = blockIdx.x;           // 0..31 stripe
    const int img = blockIdx.y;           // 0..95
    const int h0  = sy * TH;              // output row base
    const int r0  = 2 * h0;               // input row base

    const float* __restrict__ xin = x + (size_t)img * HH * WW;

    // ---- phase A: column pass, thread owns input columns (2c, 2c+1) ----
    // One aligned u64 load per row IS the FFMA2 operand. Explicit 4-deep load
    // ring guarantees MLP>=4. Hi chain via QMF: FH[t] = (-1)^(t+1) FL[7-t],
    // sign folded into the operand (negate v on even k), shared coef bank.
    {
        u64 CLd[8];                         // dup lo-coef pairs only
        #pragma unroll
        for (int t = 0; t < 8; t++) CLd[t] = pk(FL[t], FL[t]);

        const float* __restrict__ colp = xin + 2 * tid;
        u64 vbuf[4];
        #pragma unroll
        for (int p = 0; p < 4; p++)
            vbuf[p] = *(const u64*)(colp + (size_t)((r0 + p) & (HH - 1)) * WW);

        u64 aLo[4], aHi[4];                // ring over j&3
        #pragma unroll
        for (int k = 0; k < IN_R; k++) {
            u64 v = vbuf[k & 3];
            if (k + 4 < IN_R)              // prefetch row k+4 into freed slot
                vbuf[k & 3] = *(const u64*)(colp + (size_t)((r0 + k + 4) & (HH - 1)) * WW);
            u64 vh = (k & 1) ? v : (v ^ 0x8000000080000000ULL);
            #pragma unroll
            for (int j = 0; j < TH; j++) {
                const int t = k - 2 * j;
                if (t == 0) {
                    mul2(aLo[j & 3], CLd[0], v);
                    mul2(aHi[j & 3], CLd[7], vh);
                } else if (t > 0 && t < 8) {
                    fma2(aLo[j & 3], CLd[t],     v);
                    fma2(aHi[j & 3], CLd[7 - t], vh);
                }
                if (t == 7) {
                    *(u64*)&s_lo[j][2 * tid] = aLo[j & 3];
                    *(u64*)&s_hi[j][2 * tid] = aHi[j & 3];
                    if (tid < 4) {                  // wrap halo cols 512..519
                        *(u64*)&s_lo[j][WW + 2 * tid] = aLo[j & 3];
                        *(u64*)&s_hi[j][WW + 2 * tid] = aHi[j & 3];
                    }
                }
            }
        }
    }
    __syncthreads();

    // ---- phase B: row pass from smem planes (scalar, immediates) ----
    // item = (plane, j, wp): output cols 2wp, 2wp+1 of output row h0+j.
    float* __restrict__ outi = out + (size_t)img * 4 * OWW * OWW;
    const size_t SB = (size_t)OWW * OWW;

    #pragma unroll
    for (int it = 0; it < 8; it++) {
        int idx = tid + it * NT;             // 0..2047
        int wp  = idx & 127;                 // col-pair index
        int j   = (idx >> 7) & (TH - 1);     // 0..7
        int pl  = idx >> 10;                 // 0..1
        const float* __restrict__ A = pl ? &s_hi[j][0] : &s_lo[j][0];

        // window A[4wp .. 4wp+9]; 16B-stride contiguous -> conflict-free
        float4 q0 = *(const float4*)(A + 4 * wp);
        float4 q1 = *(const float4*)(A + 4 * wp + 4);
        float2 q2 = *(const float2*)(A + 4 * wp + 8);
        float v[10] = {q0.x, q0.y, q0.z, q0.w,
                       q1.x, q1.y, q1.z, q1.w,
                       q2.x, q2.y};

        float lo0 = 0.f, hi0 = 0.f, lo1 = 0.f, hi1 = 0.f;
        #pragma unroll
        for (int t = 0; t < 8; t++) {
            lo0 = fmaf(FL[t], v[t],     lo0);
            hi0 = fmaf(FH[t], v[t],     hi0);
            lo1 = fmaf(FL[t], v[t + 2], lo1);
            hi1 = fmaf(FH[t], v[t + 2], hi1);
        }

        int sbL = pl ? 1 : 0;    // row-lo result subband
        int sbH = pl ? 3 : 2;    // row-hi result subband
        size_t o = (size_t)(h0 + j) * OWW + 2 * wp;
        *(float2*)(outi + sbL * SB + o) = make_float2(lo0, lo1);
        *(float2*)(outi + sbH * SB + o) = make_float2(hi0, hi1);
    }
}

extern "C" void kernel_launch(void* const* d_in, const int* in_sizes, int n_in,
                              void* d_out, int out_size)
{
    const float* x = (const float*)d_in[0];   // (32,3,512,512) f32
    float* out = (float*)d_out;               // (32,12,256,256) f32

    dim3 grid(OWW / TH, 96);                  // (32 stripes, 96 images)
    dwt2d_db4_kernel<<<grid, NT>>>(x, out);
}